// round 2
// baseline (speedup 1.0000x reference)
#include <cuda_runtime.h>
#include <math.h>

// Problem constants
#define B   2
#define S   2048
#define D   2048
#define H   16
#define DH  128
#define BS  (B*S)          // 4096 rows
#define SCALE 0.08838834764831845f  // 1/sqrt(128)

// Scratch (device globals: allocation-free rule)
__device__ float g_q[(size_t)BS * D];
__device__ float g_k[(size_t)BS * D];
__device__ float g_v[(size_t)BS * D];
__device__ float g_ao[(size_t)BS * D];

// ---------------------------------------------------------------------------
// NT GEMM: C[M,N] = A[M,K] * W[N,K]^T  (row-major, K contiguous for both)
// 64x64 tile, 256 threads, 4x4 per-thread register blocking, K-tile 16.
// ---------------------------------------------------------------------------
__global__ __launch_bounds__(256) void gemm_nt(const float* __restrict__ A,
                                               const float* __restrict__ W,
                                               float* __restrict__ C,
                                               int M, int N, int K)
{
    __shared__ float As[16][64 + 1];
    __shared__ float Bs[16][64 + 1];

    const int t  = threadIdx.x;
    const int tx = t & 15;        // 0..15 -> n
    const int ty = t >> 4;        // 0..15 -> m
    const int m0 = blockIdx.y * 64;
    const int n0 = blockIdx.x * 64;

    float acc[4][4] = {};

    for (int k0 = 0; k0 < K; k0 += 16) {
        #pragma unroll
        for (int i = 0; i < 4; i++) {
            int idx = t + i * 256;          // 0..1023
            int mm  = idx >> 4;             // 0..63
            int kk  = idx & 15;             // 0..15
            As[kk][mm] = A[(size_t)(m0 + mm) * K + k0 + kk];
            Bs[kk][mm] = W[(size_t)(n0 + mm) * K + k0 + kk];
        }
        __syncthreads();

        #pragma unroll
        for (int kk = 0; kk < 16; kk++) {
            float a[4], b[4];
            #pragma unroll
            for (int i = 0; i < 4; i++) a[i] = As[kk][ty * 4 + i];
            #pragma unroll
            for (int j = 0; j < 4; j++) b[j] = Bs[kk][tx * 4 + j];
            #pragma unroll
            for (int i = 0; i < 4; i++)
                #pragma unroll
                for (int j = 0; j < 4; j++)
                    acc[i][j] = fmaf(a[i], b[j], acc[i][j]);
        }
        __syncthreads();
    }

    #pragma unroll
    for (int i = 0; i < 4; i++)
        #pragma unroll
        for (int j = 0; j < 4; j++)
            C[(size_t)(m0 + ty * 4 + i) * N + n0 + tx * 4 + j] = acc[i][j];
}

// ---------------------------------------------------------------------------
// Scores + causal softmax. One block per (b,h,q). Scores live in SMEM,
// single normalized write of the full weights row (zeros where masked).
// attnw layout: [b,h,q,k] contiguous.
// ---------------------------------------------------------------------------
__global__ __launch_bounds__(256) void attn_scores(float* __restrict__ attnw)
{
    const int idx = blockIdx.x;          // bh*S + q
    const int qi  = idx & (S - 1);
    const int bh  = idx >> 11;           // S = 2048 = 2^11
    const int h   = bh & (H - 1);
    const int b   = bh >> 4;             // H = 16

    __shared__ float qs[DH];
    __shared__ float sc[S];
    __shared__ float red[256];

    const int tid = threadIdx.x;
    const float* qrow = g_q + (size_t)(b * S + qi) * D + h * DH;
    for (int d = tid; d < DH; d += 256) qs[d] = qrow[d];
    __syncthreads();

    // scores for k in [0, qi]
    float lmax = -INFINITY;
    for (int kk = tid; kk <= qi; kk += 256) {
        const float* krow = g_k + (size_t)(b * S + kk) * D + h * DH;
        float s = 0.f;
        #pragma unroll
        for (int d = 0; d < DH; d += 4) {
            float4 kv = *(const float4*)(krow + d);
            s = fmaf(qs[d + 0], kv.x, s);
            s = fmaf(qs[d + 1], kv.y, s);
            s = fmaf(qs[d + 2], kv.z, s);
            s = fmaf(qs[d + 3], kv.w, s);
        }
        s *= SCALE;
        sc[kk] = s;
        lmax = fmaxf(lmax, s);
    }

    // block max
    red[tid] = lmax;
    __syncthreads();
    #pragma unroll
    for (int off = 128; off > 0; off >>= 1) {
        if (tid < off) red[tid] = fmaxf(red[tid], red[tid + off]);
        __syncthreads();
    }
    const float m = red[0];
    __syncthreads();

    // exp + sum
    float lsum = 0.f;
    for (int kk = tid; kk <= qi; kk += 256) {
        float e = __expf(sc[kk] - m);
        sc[kk] = e;
        lsum += e;
    }
    red[tid] = lsum;
    __syncthreads();
    #pragma unroll
    for (int off = 128; off > 0; off >>= 1) {
        if (tid < off) red[tid] += red[tid + off];
        __syncthreads();
    }
    const float inv = 1.f / red[0];
    __syncthreads();

    float* out = attnw + ((size_t)bh * S + qi) * S;
    for (int kk = tid; kk < S; kk += 256)
        out[kk] = (kk <= qi) ? sc[kk] * inv : 0.f;
}

// ---------------------------------------------------------------------------
// AV: attn_out[b,q, h*DH+d] = sum_{k<=q} w[b,h,q,k] * v[b,k, h*DH+d]
// One block per (b,h,q), 128 threads over d.
// ---------------------------------------------------------------------------
__global__ __launch_bounds__(128) void attn_av(const float* __restrict__ attnw)
{
    const int idx = blockIdx.x;
    const int qi  = idx & (S - 1);
    const int bh  = idx >> 11;
    const int h   = bh & (H - 1);
    const int b   = bh >> 4;

    const float* w = attnw + ((size_t)bh * S + qi) * S;
    const int d = threadIdx.x;

    __shared__ float ws[128];
    float acc = 0.f;

    for (int k0 = 0; k0 <= qi; k0 += 128) {
        __syncthreads();
        ws[d] = (k0 + d <= qi) ? w[k0 + d] : 0.f;
        __syncthreads();
        const int kmax = min(128, qi - k0 + 1);
        const float* vbase = g_v + (size_t)(b * S + k0) * D + h * DH + d;
        #pragma unroll 4
        for (int j = 0; j < kmax; j++)
            acc = fmaf(ws[j], vbase[(size_t)j * D], acc);
    }

    g_ao[(size_t)(b * S + qi) * D + h * DH + d] = acc;
}

// ---------------------------------------------------------------------------
extern "C" void kernel_launch(void* const* d_in, const int* in_sizes, int n_in,
                              void* d_out, int out_size)
{
    const float* x  = (const float*)d_in[0];
    // d_in[1] = mask (int32) — causal mask implemented directly
    const float* wq = (const float*)d_in[2];
    const float* wk = (const float*)d_in[3];
    const float* wv = (const float*)d_in[4];
    const float* wo = (const float*)d_in[5];

    float* out   = (float*)d_out;                       // [B,S,D]
    float* attnw = (float*)d_out + (size_t)BS * D;      // [B,H,S,S]

    float *q, *k, *v, *ao;
    cudaGetSymbolAddress((void**)&q,  g_q);
    cudaGetSymbolAddress((void**)&k,  g_k);
    cudaGetSymbolAddress((void**)&v,  g_v);
    cudaGetSymbolAddress((void**)&ao, g_ao);

    dim3 gsz(D / 64, BS / 64);   // N tiles x M tiles
    gemm_nt<<<gsz, 256>>>(x, wq, q, BS, D, D);
    gemm_nt<<<gsz, 256>>>(x, wk, k, BS, D, D);
    gemm_nt<<<gsz, 256>>>(x, wv, v, BS, D, D);

    attn_scores<<<B * H * S, 256>>>(attnw);
    attn_av   <<<B * H * S, 128>>>(attnw);

    gemm_nt<<<gsz, 256>>>(ao, wo, out, BS, D, D);
}

// round 3
// speedup vs baseline: 7.0601x; 7.0601x over previous
#include <cuda_runtime.h>
#include <math.h>
#include <stdint.h>

// Problem constants
#define B   2
#define S   2048
#define D   2048
#define H   16
#define DH  128
#define BS  (B*S)          // 4096 rows
#define SCALE 0.08838834764831845f  // 1/sqrt(128)

// Scratch (device globals: allocation-free rule)
__device__ float g_q[(size_t)BS * D];
__device__ float g_k[(size_t)BS * D];
__device__ float g_v[(size_t)BS * D];
__device__ float g_ao[(size_t)BS * D];

__device__ __forceinline__ uint32_t f2tf32(float f) {
    uint32_t r;
    asm("cvt.rna.tf32.f32 %0, %1;" : "=r"(r) : "f"(f));
    return r;
}

__device__ __forceinline__ void mma8(float* c, const uint32_t* a, const uint32_t* b) {
    asm volatile(
        "mma.sync.aligned.m16n8k8.row.col.f32.tf32.tf32.f32 "
        "{%0,%1,%2,%3}, {%4,%5,%6,%7}, {%8,%9}, {%0,%1,%2,%3};"
        : "+f"(c[0]), "+f"(c[1]), "+f"(c[2]), "+f"(c[3])
        : "r"(a[0]), "r"(a[1]), "r"(a[2]), "r"(a[3]), "r"(b[0]), "r"(b[1]));
}

// ---------------------------------------------------------------------------
// tf32 tensor-core GEMM, 128x128 tile, 256 threads (8 warps: 4m x 2n).
//   C[m][n] = alpha * sum_k A[m][k] * Bop[k][n]
//   BNN=false: B given as [N,K] row-major (NT, k-contiguous)  -> Bop = B^T
//   BNN=true : B given as [K,N] row-major (NN, n-contiguous)
//   CAUSAL: skip blocks with n0 > m0 (scores)
//   KLIM:   k-loop stops at m0+128 (AV: weights above diagonal are zero)
// Batch via blockIdx.z: offset = (bz>>4)*xB + (bz&15)*xH
// ---------------------------------------------------------------------------
template<bool BNN, bool CAUSAL, bool KLIM>
__global__ __launch_bounds__(256, 2) void gemm_tf32(
    const float* __restrict__ A, const float* __restrict__ Bm, float* __restrict__ C,
    int M, int N, int K, int lda, int ldb, int ldc,
    long aB, long aH, long bB, long bH, long cB, long cH, float alpha)
{
    const int m0 = blockIdx.y * 128;
    const int n0 = blockIdx.x * 128;
    if (CAUSAL && n0 > m0) return;

    const int bz = blockIdx.z, bb = bz >> 4, hh = bz & 15;
    A  += (size_t)bb * aB + (size_t)hh * aH;
    Bm += (size_t)bb * bB + (size_t)hh * bH;
    C  += (size_t)bb * cB + (size_t)hh * cH;

    __shared__ uint32_t As[16][136];
    __shared__ uint32_t Bs[16][136];

    const int t    = threadIdx.x;
    const int warp = t >> 5, lane = t & 31;
    const int wm = (warp >> 1) * 32;   // warp row offset in tile
    const int wn = (warp & 1) * 64;    // warp col offset in tile
    const int g  = lane >> 2, c = lane & 3;

    float acc[2][8][4];
    #pragma unroll
    for (int i = 0; i < 2; i++)
        #pragma unroll
        for (int j = 0; j < 8; j++)
            #pragma unroll
            for (int r = 0; r < 4; r++) acc[i][j][r] = 0.f;

    // staging indices
    const int arow = t >> 2;            // 0..63
    const int akq  = (t & 3) * 4;       // k quad
    const int brow = t >> 4;            // 0..15 (NN)
    const int bcol = (t & 15) * 4;      // 0..60 (NN)

    int kEnd = K;
    if (KLIM) kEnd = min(K, m0 + 128);

    for (int k0 = 0; k0 < kEnd; k0 += 16) {
        // stage A: [BM=128][BK=16] -> As[k][m]
        #pragma unroll
        for (int i = 0; i < 2; i++) {
            const int m = arow + i * 64;
            const float4 v = *reinterpret_cast<const float4*>(
                A + (size_t)(m0 + m) * lda + k0 + akq);
            As[akq + 0][m] = f2tf32(v.x);
            As[akq + 1][m] = f2tf32(v.y);
            As[akq + 2][m] = f2tf32(v.z);
            As[akq + 3][m] = f2tf32(v.w);
        }
        // stage B -> Bs[k][n]
        if (BNN) {
            #pragma unroll
            for (int i = 0; i < 2; i++) {
                const int n = bcol + i * 64;
                const float4 v = *reinterpret_cast<const float4*>(
                    Bm + (size_t)(k0 + brow) * ldb + n0 + n);
                Bs[brow][n + 0] = f2tf32(v.x);
                Bs[brow][n + 1] = f2tf32(v.y);
                Bs[brow][n + 2] = f2tf32(v.z);
                Bs[brow][n + 3] = f2tf32(v.w);
            }
        } else {
            #pragma unroll
            for (int i = 0; i < 2; i++) {
                const int n = arow + i * 64;
                const float4 v = *reinterpret_cast<const float4*>(
                    Bm + (size_t)(n0 + n) * ldb + k0 + akq);
                Bs[akq + 0][n] = f2tf32(v.x);
                Bs[akq + 1][n] = f2tf32(v.y);
                Bs[akq + 2][n] = f2tf32(v.z);
                Bs[akq + 3][n] = f2tf32(v.w);
            }
        }
        __syncthreads();

        #pragma unroll
        for (int ks = 0; ks < 16; ks += 8) {
            uint32_t af[2][4], bf[8][2];
            #pragma unroll
            for (int i = 0; i < 2; i++) {
                const int mb = wm + i * 16;
                af[i][0] = As[ks + c][mb + g];
                af[i][1] = As[ks + c][mb + g + 8];
                af[i][2] = As[ks + c + 4][mb + g];
                af[i][3] = As[ks + c + 4][mb + g + 8];
            }
            #pragma unroll
            for (int j = 0; j < 8; j++) {
                const int nb = wn + j * 8 + g;
                bf[j][0] = Bs[ks + c][nb];
                bf[j][1] = Bs[ks + c + 4][nb];
            }
            #pragma unroll
            for (int i = 0; i < 2; i++)
                #pragma unroll
                for (int j = 0; j < 8; j++)
                    mma8(acc[i][j], af[i], bf[j]);
        }
        __syncthreads();
    }

    // epilogue
    #pragma unroll
    for (int i = 0; i < 2; i++) {
        #pragma unroll
        for (int j = 0; j < 8; j++) {
            const int mrow = m0 + wm + i * 16 + g;
            const int ncol = n0 + wn + j * 8 + 2 * c;
            float2 v0 = make_float2(alpha * acc[i][j][0], alpha * acc[i][j][1]);
            float2 v1 = make_float2(alpha * acc[i][j][2], alpha * acc[i][j][3]);
            *reinterpret_cast<float2*>(C + (size_t)mrow * ldc + ncol)       = v0;
            *reinterpret_cast<float2*>(C + (size_t)(mrow + 8) * ldc + ncol) = v1;
        }
    }
}

// ---------------------------------------------------------------------------
// Row softmax in place over raw scores. One block per (b,h,q) row.
// Reads k <= qi, writes the full row (zeros above the diagonal).
// ---------------------------------------------------------------------------
__global__ __launch_bounds__(256) void softmax_rows(float* __restrict__ attnw)
{
    const int idx = blockIdx.x;          // bh*S + q
    const int qi  = idx & (S - 1);

    __shared__ float sc[S];
    __shared__ float red[256];

    const int tid = threadIdx.x;
    float* row = attnw + (size_t)idx * S;

    float lmax = -INFINITY;
    for (int kk = tid; kk <= qi; kk += 256) {
        const float s = row[kk];
        sc[kk] = s;
        lmax = fmaxf(lmax, s);
    }
    red[tid] = lmax;
    __syncthreads();
    #pragma unroll
    for (int off = 128; off > 0; off >>= 1) {
        if (tid < off) red[tid] = fmaxf(red[tid], red[tid + off]);
        __syncthreads();
    }
    const float m = red[0];
    __syncthreads();

    float lsum = 0.f;
    for (int kk = tid; kk <= qi; kk += 256) {
        const float e = __expf(sc[kk] - m);
        sc[kk] = e;
        lsum += e;
    }
    red[tid] = lsum;
    __syncthreads();
    #pragma unroll
    for (int off = 128; off > 0; off >>= 1) {
        if (tid < off) red[tid] += red[tid + off];
        __syncthreads();
    }
    const float inv = 1.f / red[0];
    __syncthreads();

    for (int kk = tid; kk < S; kk += 256)
        row[kk] = (kk <= qi) ? sc[kk] * inv : 0.f;
}

// ---------------------------------------------------------------------------
extern "C" void kernel_launch(void* const* d_in, const int* in_sizes, int n_in,
                              void* d_out, int out_size)
{
    const float* x  = (const float*)d_in[0];
    // d_in[1] = mask (int32) — causal mask implemented directly
    const float* wq = (const float*)d_in[2];
    const float* wk = (const float*)d_in[3];
    const float* wv = (const float*)d_in[4];
    const float* wo = (const float*)d_in[5];

    float* out   = (float*)d_out;                       // [B,S,D]
    float* attnw = (float*)d_out + (size_t)BS * D;      // [B,H,S,S]

    float *q, *k, *v, *ao;
    cudaGetSymbolAddress((void**)&q,  g_q);
    cudaGetSymbolAddress((void**)&k,  g_k);
    cudaGetSymbolAddress((void**)&v,  g_v);
    cudaGetSymbolAddress((void**)&ao, g_ao);

    // 1) Q/K/V projections: C[BS,D] = X[BS,D] * W[D,D]^T   (NT)
    {
        dim3 grid(D / 128, BS / 128, 1);
        gemm_tf32<false, false, false><<<grid, 256>>>(
            x, wq, q, BS, D, D, D, D, D, 0, 0, 0, 0, 0, 0, 1.0f);
        gemm_tf32<false, false, false><<<grid, 256>>>(
            x, wk, k, BS, D, D, D, D, D, 0, 0, 0, 0, 0, 0, 1.0f);
        gemm_tf32<false, false, false><<<grid, 256>>>(
            x, wv, v, BS, D, D, D, D, D, 0, 0, 0, 0, 0, 0, 1.0f);
    }

    // 2) Scores: per (b,h)  Sc[S,S] = scale * Q[S,DH] * K[S,DH]^T  (NT, causal)
    {
        dim3 grid(S / 128, S / 128, B * H);
        gemm_tf32<false, true, false><<<grid, 256>>>(
            q, k, attnw, S, S, DH, D, D, S,
            (long)S * D, DH,            // A strides (b, h)
            (long)S * D, DH,            // B strides
            (long)H * S * S, (long)S * S,  // C strides
            SCALE);
    }

    // 3) Row softmax in place
    softmax_rows<<<B * H * S, 256>>>(attnw);

    // 4) AV: per (b,h)  AO[S,DH] = W[S,S] * V[S,DH]   (NN, k limited to diagonal)
    {
        dim3 grid(1, S / 128, B * H);
        gemm_tf32<true, false, true><<<grid, 256>>>(
            attnw, v, ao, S, DH, S, S, D, D,
            (long)H * S * S, (long)S * S,
            (long)S * D, DH,
            (long)S * D, DH,
            1.0f);
    }

    // 5) Output projection: out[BS,D] = AO[BS,D] * WO[D,D]^T  (NT)
    {
        dim3 grid(D / 128, BS / 128, 1);
        gemm_tf32<false, false, false><<<grid, 256>>>(
            ao, wo, out, BS, D, D, D, D, D, 0, 0, 0, 0, 0, 0, 1.0f);
    }
}